// round 1
// baseline (speedup 1.0000x reference)
#include <cuda_runtime.h>
#include <math.h>

#define SEQ 2048
#define HID 3072
#define NH 24
#define NKV 8
#define HD 128
#define ROTD 96
#define QKV_N 5120   // NH*HD + 2*NKV*HD
#define NREP 3       // NH / NKV

// ---- static scratch (allocation-free contract) ----
__device__ float g_qkv[SEQ * QKV_N];        // (s, 5120)
__device__ float g_q  [NH * SEQ * HD];      // (h, s, d)  roped
__device__ float g_k  [NH * SEQ * HD];      // (h, s, d)  roped, GQA-replicated
__device__ float g_vt [NH * HD * SEQ];      // (h, d, s)  transposed, replicated
__device__ float g_ao [SEQ * HID];          // (s, h*HD+d)

// ============================================================
// Generic NT GEMM: C[m,n] = alpha * sum_k A[m,k]*B[n,k]
// 128x128 tile, BK=16, 256 threads, 8x8 per-thread microtile.
// Batched via blockIdx.z with long-long strides.
// causal=1: skip blocks fully above the diagonal (col_start > row_end).
// All M,N multiples of 128; K multiple of 16 (true for every call here).
// ============================================================
__global__ __launch_bounds__(256) void gemm_nt(
    const float* __restrict__ A, const float* __restrict__ B, float* __restrict__ C,
    int M, int N, int K, int lda, int ldb, int ldc,
    long long sA, long long sB, long long sC,
    float alpha, int causal)
{
    if (causal && (int)blockIdx.x * 128 > (int)blockIdx.y * 128 + 127) return;

    __shared__ float As[16][128];
    __shared__ float Bs[16][128];

    const float* Ab = A + (long long)blockIdx.z * sA + (long long)blockIdx.y * 128 * lda;
    const float* Bb = B + (long long)blockIdx.z * sB + (long long)blockIdx.x * 128 * ldb;
    float*       Cb = C + (long long)blockIdx.z * sC;

    const int tid  = threadIdx.x;
    const int lrow = tid >> 2;          // 0..63
    const int lcol = (tid & 3) << 2;    // 0,4,8,12
    const int ty   = tid >> 4;          // 0..15
    const int tx   = tid & 15;          // 0..15

    float acc[8][8];
    #pragma unroll
    for (int i = 0; i < 8; i++)
        #pragma unroll
        for (int j = 0; j < 8; j++) acc[i][j] = 0.0f;

    for (int k0 = 0; k0 < K; k0 += 16) {
        #pragma unroll
        for (int i = 0; i < 2; i++) {
            const int r = lrow + i * 64;
            float4 va = *(const float4*)(Ab + (long long)r * lda + k0 + lcol);
            As[lcol + 0][r] = va.x;
            As[lcol + 1][r] = va.y;
            As[lcol + 2][r] = va.z;
            As[lcol + 3][r] = va.w;
            float4 vb = *(const float4*)(Bb + (long long)r * ldb + k0 + lcol);
            Bs[lcol + 0][r] = vb.x;
            Bs[lcol + 1][r] = vb.y;
            Bs[lcol + 2][r] = vb.z;
            Bs[lcol + 3][r] = vb.w;
        }
        __syncthreads();

        #pragma unroll
        for (int kk = 0; kk < 16; kk++) {
            float a[8], b[8];
            #pragma unroll
            for (int i = 0; i < 8; i++) a[i] = As[kk][ty * 8 + i];
            #pragma unroll
            for (int j = 0; j < 8; j++) b[j] = Bs[kk][tx * 8 + j];
            #pragma unroll
            for (int i = 0; i < 8; i++)
                #pragma unroll
                for (int j = 0; j < 8; j++)
                    acc[i][j] += a[i] * b[j];
        }
        __syncthreads();
    }

    const int row0 = blockIdx.y * 128 + ty * 8;
    const int col0 = blockIdx.x * 128 + tx * 8;
    #pragma unroll
    for (int i = 0; i < 8; i++) {
        float* cp = Cb + (long long)(row0 + i) * ldc + col0;
        #pragma unroll
        for (int j = 0; j < 8; j += 4) {
            float4 v;
            v.x = alpha * acc[i][j + 0];
            v.y = alpha * acc[i][j + 1];
            v.z = alpha * acc[i][j + 2];
            v.w = alpha * acc[i][j + 3];
            *(float4*)(cp + j) = v;
        }
    }
}

// ============================================================
// RoPE + rearrange: qkv(s,5120) -> q(h,s,d), k(h,s,d) repl, vT(h,d,s) repl
// ============================================================
__global__ void rope_kernel(const float* __restrict__ qkv,
                            const float* __restrict__ cosb,
                            const float* __restrict__ sinb)
{
    const int s = blockIdx.x;
    const float* row = qkv + (long long)s * QKV_N;
    const float* cs = cosb + (long long)s * ROTD;
    const float* sn = sinb + (long long)s * ROTD;

    for (int idx = threadIdx.x; idx < QKV_N; idx += blockDim.x) {
        const int d = idx & (HD - 1);
        float x = row[idx];
        float outv = x;
        if (idx < NH * HD + NKV * HD) {  // q or k gets RoPE
            if (d < ROTD / 2)       outv = x * cs[d] - row[idx + ROTD / 2] * sn[d];
            else if (d < ROTD)      outv = x * cs[d] + row[idx - ROTD / 2] * sn[d];
        }
        if (idx < NH * HD) {
            const int h = idx >> 7;
            g_q[((long long)h * SEQ + s) * HD + d] = outv;
        } else if (idx < NH * HD + NKV * HD) {
            const int kh = (idx - NH * HD) >> 7;
            #pragma unroll
            for (int r = 0; r < NREP; r++)
                g_k[((long long)(kh * NREP + r) * SEQ + s) * HD + d] = outv;
        } else {
            const int vh = (idx - NH * HD - NKV * HD) >> 7;
            #pragma unroll
            for (int r = 0; r < NREP; r++)
                g_vt[((long long)(vh * NREP + r) * HD + d) * SEQ + s] = outv;
        }
    }
}

// ============================================================
// Row softmax with causal zeroing. One block (256 thr) per (q,h) row.
// Reads the n=q+1 valid scores once into registers; writes exact 0 for k>q.
// ============================================================
__global__ __launch_bounds__(256) void softmax_kernel(float* __restrict__ attnw)
{
    const int q = blockIdx.x;
    const int h = blockIdx.y;
    float* row = attnw + ((long long)h * SEQ + q) * SEQ;
    const int n = q + 1;
    const int tid = threadIdx.x;

    __shared__ float red[256];

    float vals[8];
    float m = -1e30f;
    #pragma unroll
    for (int i = 0; i < 8; i++) {
        const int idx = tid + i * 256;
        vals[i] = (idx < n) ? row[idx] : -1e30f;
        m = fmaxf(m, vals[i]);
    }
    red[tid] = m;
    __syncthreads();
    for (int s2 = 128; s2 > 0; s2 >>= 1) {
        if (tid < s2) red[tid] = fmaxf(red[tid], red[tid + s2]);
        __syncthreads();
    }
    m = red[0];
    __syncthreads();

    float sum = 0.0f;
    #pragma unroll
    for (int i = 0; i < 8; i++) {
        const int idx = tid + i * 256;
        vals[i] = (idx < n) ? expf(vals[i] - m) : 0.0f;
        sum += vals[i];
    }
    red[tid] = sum;
    __syncthreads();
    for (int s2 = 128; s2 > 0; s2 >>= 1) {
        if (tid < s2) red[tid] += red[tid + s2];
        __syncthreads();
    }
    const float inv = 1.0f / red[0];

    #pragma unroll
    for (int i = 0; i < 8; i++) {
        const int idx = tid + i * 256;
        row[idx] = vals[i] * inv;   // zero for idx >= n
    }
}

// ============================================================
extern "C" void kernel_launch(void* const* d_in, const int* in_sizes, int n_in,
                              void* d_out, int out_size)
{
    const float* hidden = (const float*)d_in[0];  // (1,2048,3072)
    const float* cosb   = (const float*)d_in[1];  // (1,2048,96)
    const float* sinb   = (const float*)d_in[2];  // (1,2048,96)
    // d_in[3] = attention_mask (causal; applied analytically)
    const float* w_qkv  = (const float*)d_in[4];  // (5120,3072)
    const float* w_o    = (const float*)d_in[5];  // (3072,3072)

    float* out   = (float*)d_out;                          // (2048,3072)
    float* attnw = out + (long long)SEQ * HID;             // (24,2048,2048)

    float *qkvb, *qb, *kb, *vtb, *aob;
    cudaGetSymbolAddress((void**)&qkvb, g_qkv);
    cudaGetSymbolAddress((void**)&qb,   g_q);
    cudaGetSymbolAddress((void**)&kb,   g_k);
    cudaGetSymbolAddress((void**)&vtb,  g_vt);
    cudaGetSymbolAddress((void**)&aob,  g_ao);

    const float scale = 0.08838834764831843f;  // 128^-0.5
    dim3 blk(256);

    // 1) QKV projection: (2048x3072) x (5120x3072)^T -> (2048x5120)
    gemm_nt<<<dim3(QKV_N / 128, SEQ / 128, 1), blk>>>(
        hidden, w_qkv, qkvb, SEQ, QKV_N, HID, HID, HID, QKV_N,
        0, 0, 0, 1.0f, 0);

    // 2) RoPE + rearrange + GQA replicate + V transpose
    rope_kernel<<<SEQ, 512>>>(qkvb, cosb, sinb);

    // 3) Scores: per head, (2048x128) x (2048x128)^T * scale, causal block-skip
    gemm_nt<<<dim3(SEQ / 128, SEQ / 128, NH), blk>>>(
        qb, kb, attnw, SEQ, SEQ, HD, HD, HD, SEQ,
        (long long)SEQ * HD, (long long)SEQ * HD, (long long)SEQ * SEQ,
        scale, 1);

    // 4) Causal softmax (writes the attn_weights output in place)
    softmax_kernel<<<dim3(SEQ, NH), blk>>>(attnw);

    // 5) AV: per head, (2048x2048) x (128x2048)^T -> attn_out (s, h*128+d)
    gemm_nt<<<dim3(HD / 128, SEQ / 128, NH), blk>>>(
        attnw, vtb, aob, SEQ, HD, SEQ, SEQ, SEQ, HID,
        (long long)SEQ * SEQ, (long long)HD * SEQ, (long long)HD,
        1.0f, 0);

    // 6) Output projection: (2048x3072) x (3072x3072)^T -> out
    gemm_nt<<<dim3(HID / 128, SEQ / 128, 1), blk>>>(
        aob, w_o, out, SEQ, HID, HID, HID, HID, HID,
        0, 0, 0, 1.0f, 0);
}

// round 3
// speedup vs baseline: 2.4697x; 2.4697x over previous
#include <cuda_runtime.h>
#include <math.h>
#include <stdint.h>

#define SEQ 2048
#define HID 3072
#define NH 24
#define NKV 8
#define HD 128
#define ROTD 96
#define QKV_N 5120   // NH*HD + 2*NKV*HD
#define NREP 3       // NH / NKV

// ---- static scratch (allocation-free contract) ----
__device__ float g_qkv[SEQ * QKV_N];        // (s, 5120)
__device__ float g_q  [NH * SEQ * HD];      // (h, s, d)  roped
__device__ float g_k  [NH * SEQ * HD];      // (h, s, d)  roped, GQA-replicated
__device__ float g_vt [NH * HD * SEQ];      // (h, d, s)  transposed, replicated
__device__ float g_ao [SEQ * HID];          // (s, h*HD+d)

// ============================================================
// helpers
// ============================================================
__device__ __forceinline__ uint32_t s2u(const void* p) {
    uint32_t a;
    asm("{ .reg .u64 t; cvta.to.shared.u64 t, %1; cvt.u32.u64 %0, t; }" : "=r"(a) : "l"(p));
    return a;
}
__device__ __forceinline__ uint32_t f2tf(float f) {
    uint32_t r;
    asm("cvt.rna.tf32.f32 %0, %1;" : "=r"(r) : "f"(f));
    return r;
}
#define CP16(smem_u32, gptr) \
    asm volatile("cp.async.cg.shared.global [%0], [%1], 16;" :: "r"(smem_u32), "l"(gptr) : "memory")
#define CP_COMMIT() asm volatile("cp.async.commit_group;" ::: "memory")
#define CP_WAIT(n)  asm volatile("cp.async.wait_group %0;" :: "n"(n) : "memory")

#define MMA_TF32(d, a, b) \
    asm volatile("mma.sync.aligned.m16n8k8.row.col.f32.tf32.tf32.f32 " \
        "{%0,%1,%2,%3}, {%4,%5,%6,%7}, {%8,%9}, {%0,%1,%2,%3};" \
        : "+f"((d)[0]), "+f"((d)[1]), "+f"((d)[2]), "+f"((d)[3]) \
        : "r"((a)[0]), "r"((a)[1]), "r"((a)[2]), "r"((a)[3]), \
          "r"((b)[0]), "r"((b)[1]))

// ============================================================
// Tensor-core NT GEMM via mma.sync tf32:
//   C[m,n] = alpha * sum_k A[m,k]*B[n,k]
// 128x128 CTA tile, BK=32, 256 threads (8 warps, 2x4), warp tile 64x32.
// cp.async double-buffered smem, padded stride 36 floats (conflict-free).
// causal:   skip output blocks fully above the diagonal (scores)
// causal_k: clamp K to (by+1)*128 (AV — attnw zero above diagonal)
// All M,N multiples of 128; K multiple of 32.
// ============================================================
#define SSTR 36                    // padded smem row stride (floats)
#define TILEF (128 * SSTR)         // floats per tile (A or B)
#define STAGEF (2 * TILEF)         // floats per stage (A+B)
#define SMEM_BYTES (2 * STAGEF * 4)

__global__ __launch_bounds__(256, 2) void gemm_mma(
    const float* __restrict__ A, const float* __restrict__ B, float* __restrict__ C,
    int K, int lda, int ldb, int ldc,
    long long sA, long long sB, long long sC,
    float alpha, int causal, int causal_k)
{
    const int bx = blockIdx.x, by = blockIdx.y, bz = blockIdx.z;
    if (causal && bx * 128 > by * 128 + 127) return;
    int Keff = K;
    if (causal_k) { int km = (by + 1) * 128; if (km < Keff) Keff = km; }
    const int nch = Keff >> 5;

    extern __shared__ float sm[];

    const int tid = threadIdx.x;
    const int wid = tid >> 5;
    const int lid = tid & 31;
    const int wm  = wid & 1;       // warp row: 0..1 (64 rows each)
    const int wn  = wid >> 1;      // warp col: 0..3 (32 cols each)
    const int g   = lid >> 2;      // 0..7
    const int t   = lid & 3;       // 0..3

    const float* Ab = A + bz * sA + (long long)by * 128 * lda;
    const float* Bb = B + bz * sB + (long long)bx * 128 * ldb;

    // cp.async mapping: each thread copies one row-half (16 floats = 4x float4)
    const int lrow = tid >> 1;            // 0..127
    const int lcb  = (tid & 1) * 16;      // col base: 0 or 16
    const float* ag = Ab + (long long)lrow * lda + lcb;
    const float* bg = Bb + (long long)lrow * ldb + lcb;
    const uint32_t smu = s2u(sm);
    const uint32_t sa_off = (uint32_t)(lrow * SSTR + lcb) * 4;

    auto issue = [&](int c, int s) {
        const uint32_t sab = smu + (uint32_t)(s * STAGEF) * 4 + sa_off;
        const uint32_t sbb = sab + (uint32_t)TILEF * 4;
        const float* ap = ag + c * 32;
        const float* bp = bg + c * 32;
        #pragma unroll
        for (int i = 0; i < 4; i++) {
            CP16(sab + i * 16, ap + i * 4);
            CP16(sbb + i * 16, bp + i * 4);
        }
    };

    float acc[4][4][4];
    #pragma unroll
    for (int mf = 0; mf < 4; mf++)
        #pragma unroll
        for (int nf = 0; nf < 4; nf++)
            #pragma unroll
            for (int i = 0; i < 4; i++) acc[mf][nf][i] = 0.0f;

    issue(0, 0); CP_COMMIT();
    if (nch > 1) { issue(1, 1); CP_COMMIT(); }

    for (int c = 0; c < nch; c++) {
        const int s = c & 1;
        if (c + 1 < nch) { CP_WAIT(1); } else { CP_WAIT(0); }
        __syncthreads();

        const float* As = sm + s * STAGEF + (wm * 64 + g) * SSTR;
        const float* Bs = sm + s * STAGEF + TILEF + (wn * 32 + g) * SSTR;

        #pragma unroll
        for (int kk = 0; kk < 4; kk++) {
            const int kb = kk * 8 + t;
            uint32_t af[4][4], bf[4][2];
            #pragma unroll
            for (int mf = 0; mf < 4; mf++) {
                const float* p = As + mf * 16 * SSTR + kb;
                af[mf][0] = f2tf(p[0]);
                af[mf][1] = f2tf(p[8 * SSTR]);
                af[mf][2] = f2tf(p[4]);
                af[mf][3] = f2tf(p[8 * SSTR + 4]);
            }
            #pragma unroll
            for (int nf = 0; nf < 4; nf++) {
                const float* p = Bs + nf * 8 * SSTR + kb;
                bf[nf][0] = f2tf(p[0]);
                bf[nf][1] = f2tf(p[4]);
            }
            #pragma unroll
            for (int mf = 0; mf < 4; mf++)
                #pragma unroll
                for (int nf = 0; nf < 4; nf++)
                    MMA_TF32(acc[mf][nf], af[mf], bf[nf]);
        }
        __syncthreads();
        if (c + 2 < nch) { issue(c + 2, s); CP_COMMIT(); }
    }

    // epilogue: direct global store (float2 per fragment half-row)
    float* Cb = C + bz * sC;
    #pragma unroll
    for (int mf = 0; mf < 4; mf++) {
        const int r0 = by * 128 + wm * 64 + mf * 16 + g;
        #pragma unroll
        for (int nf = 0; nf < 4; nf++) {
            const int c0 = bx * 128 + wn * 32 + nf * 8 + 2 * t;
            float* cp = Cb + (long long)r0 * ldc + c0;
            float2 v0, v1;
            v0.x = alpha * acc[mf][nf][0];
            v0.y = alpha * acc[mf][nf][1];
            v1.x = alpha * acc[mf][nf][2];
            v1.y = alpha * acc[mf][nf][3];
            *(float2*)cp = v0;
            *(float2*)(cp + 8 * ldc) = v1;
        }
    }
}

// ============================================================
// RoPE + rearrange: qkv(s,5120) -> q(h,s,d), k(h,s,d) repl, vT(h,d,s) repl
// ============================================================
__global__ void rope_kernel(const float* __restrict__ qkv,
                            const float* __restrict__ cosb,
                            const float* __restrict__ sinb)
{
    const int s = blockIdx.x;
    const float* row = qkv + (long long)s * QKV_N;
    const float* cs = cosb + (long long)s * ROTD;
    const float* sn = sinb + (long long)s * ROTD;

    for (int idx = threadIdx.x; idx < QKV_N; idx += blockDim.x) {
        const int d = idx & (HD - 1);
        float x = row[idx];
        float outv = x;
        if (idx < NH * HD + NKV * HD) {
            if (d < ROTD / 2)       outv = x * cs[d] - row[idx + ROTD / 2] * sn[d];
            else if (d < ROTD)      outv = x * cs[d] + row[idx - ROTD / 2] * sn[d];
        }
        if (idx < NH * HD) {
            const int h = idx >> 7;
            g_q[((long long)h * SEQ + s) * HD + d] = outv;
        } else if (idx < NH * HD + NKV * HD) {
            const int kh = (idx - NH * HD) >> 7;
            #pragma unroll
            for (int r = 0; r < NREP; r++)
                g_k[((long long)(kh * NREP + r) * SEQ + s) * HD + d] = outv;
        } else {
            const int vh = (idx - NH * HD - NKV * HD) >> 7;
            #pragma unroll
            for (int r = 0; r < NREP; r++)
                g_vt[((long long)(vh * NREP + r) * HD + d) * SEQ + s] = outv;
        }
    }
}

// ============================================================
// Row softmax with causal zeroing. One block (256 thr) per (q,h) row.
// ============================================================
__global__ __launch_bounds__(256) void softmax_kernel(float* __restrict__ attnw)
{
    const int q = blockIdx.x;
    const int h = blockIdx.y;
    float* row = attnw + ((long long)h * SEQ + q) * SEQ;
    const int n = q + 1;
    const int tid = threadIdx.x;

    __shared__ float red[256];

    float vals[8];
    float m = -1e30f;
    #pragma unroll
    for (int i = 0; i < 8; i++) {
        const int idx = tid + i * 256;
        vals[i] = (idx < n) ? row[idx] : -1e30f;
        m = fmaxf(m, vals[i]);
    }
    red[tid] = m;
    __syncthreads();
    for (int s2 = 128; s2 > 0; s2 >>= 1) {
        if (tid < s2) red[tid] = fmaxf(red[tid], red[tid + s2]);
        __syncthreads();
    }
    m = red[0];
    __syncthreads();

    float sum = 0.0f;
    #pragma unroll
    for (int i = 0; i < 8; i++) {
        const int idx = tid + i * 256;
        vals[i] = (idx < n) ? expf(vals[i] - m) : 0.0f;
        sum += vals[i];
    }
    red[tid] = sum;
    __syncthreads();
    for (int s2 = 128; s2 > 0; s2 >>= 1) {
        if (tid < s2) red[tid] += red[tid + s2];
        __syncthreads();
    }
    const float inv = 1.0f / red[0];

    #pragma unroll
    for (int i = 0; i < 8; i++) {
        const int idx = tid + i * 256;
        row[idx] = vals[i] * inv;
    }
}

// ============================================================
extern "C" void kernel_launch(void* const* d_in, const int* in_sizes, int n_in,
                              void* d_out, int out_size)
{
    const float* hidden = (const float*)d_in[0];
    const float* cosb   = (const float*)d_in[1];
    const float* sinb   = (const float*)d_in[2];
    // d_in[3] = attention_mask (causal; applied analytically)
    const float* w_qkv  = (const float*)d_in[4];
    const float* w_o    = (const float*)d_in[5];

    float* out   = (float*)d_out;                 // (2048,3072)
    float* attnw = out + (long long)SEQ * HID;    // (24,2048,2048)

    float *qkvb, *qb, *kb, *vtb, *aob;
    cudaGetSymbolAddress((void**)&qkvb, g_qkv);
    cudaGetSymbolAddress((void**)&qb,   g_q);
    cudaGetSymbolAddress((void**)&kb,   g_k);
    cudaGetSymbolAddress((void**)&vtb,  g_vt);
    cudaGetSymbolAddress((void**)&aob,  g_ao);

    static int configured = 0;
    if (!configured) {
        cudaFuncSetAttribute(gemm_mma, cudaFuncAttributeMaxDynamicSharedMemorySize, SMEM_BYTES);
        configured = 1;
    }

    const float scale = 0.08838834764831843f;  // 128^-0.5
    dim3 blk(256);

    // 1) QKV projection: (2048x3072) x (5120x3072)^T -> (2048x5120)
    gemm_mma<<<dim3(QKV_N / 128, SEQ / 128, 1), blk, SMEM_BYTES>>>(
        hidden, w_qkv, qkvb, HID, HID, HID, QKV_N,
        0, 0, 0, 1.0f, 0, 0);

    // 2) RoPE + rearrange + GQA replicate + V transpose
    rope_kernel<<<SEQ, 512>>>(qkvb, cosb, sinb);

    // 3) Scores: per head, (2048x128) x (2048x128)^T * scale, causal block-skip
    gemm_mma<<<dim3(SEQ / 128, SEQ / 128, NH), blk, SMEM_BYTES>>>(
        qb, kb, attnw, HD, HD, HD, SEQ,
        (long long)SEQ * HD, (long long)SEQ * HD, (long long)SEQ * SEQ,
        scale, 1, 0);

    // 4) Causal softmax (writes the attn_weights output in place)
    softmax_kernel<<<dim3(SEQ, NH), blk>>>(attnw);

    // 5) AV: per head, (2048x2048) x (128x2048)^T, K clamped causally
    gemm_mma<<<dim3(HD / 128, SEQ / 128, NH), blk, SMEM_BYTES>>>(
        attnw, vtb, aob, SEQ, SEQ, SEQ, HID,
        (long long)SEQ * SEQ, (long long)HD * SEQ, (long long)HD,
        1.0f, 0, 1);

    // 6) Output projection: (2048x3072) x (3072x3072)^T -> out
    gemm_mma<<<dim3(HID / 128, SEQ / 128, 1), blk, SMEM_BYTES>>>(
        aob, w_o, out, HID, HID, HID, HID,
        0, 0, 0, 1.0f, 0, 0);
}

// round 7
// speedup vs baseline: 2.6064x; 1.0554x over previous
#include <cuda_runtime.h>
#include <math.h>
#include <stdint.h>

#define SEQ 2048
#define HID 3072
#define NH 24
#define NKV 8
#define HD 128
#define ROTD 96
#define QKV_N 5120   // NH*HD + 2*NKV*HD
#define NREP 3       // NH / NKV

// ---- static scratch (allocation-free contract) ----
__device__ float g_qkv [SEQ * QKV_N];       // (s, 5120)
__device__ float g_q   [NH * SEQ * HD];     // (h, s, d)  roped, tf32-rounded
__device__ float g_k   [NH * SEQ * HD];     // (h, s, d)  roped, replicated, rounded
__device__ float g_vt  [NH * HD * SEQ];     // (h, d, s)  transposed, replicated, rounded
__device__ float g_ao  [SEQ * HID];         // (s, h*HD+d) tf32-rounded
__device__ float g_hid [SEQ * HID];         // tf32-rounded hidden
__device__ float g_wqkv[QKV_N * HID];       // tf32-rounded w_qkv
__device__ float g_wo  [HID * HID];         // tf32-rounded w_o

// ============================================================
// helpers
// ============================================================
__device__ __forceinline__ uint32_t s2u(const void* p) {
    uint32_t a;
    asm("{ .reg .u64 t; cvta.to.shared.u64 t, %1; cvt.u32.u64 %0, t; }" : "=r"(a) : "l"(p));
    return a;
}
__device__ __forceinline__ uint32_t f2tf(float f) {
    uint32_t r;
    asm("cvt.rna.tf32.f32 %0, %1;" : "=r"(r) : "f"(f));
    return r;
}
__device__ __forceinline__ float f2tff(float f) {
    return __uint_as_float(f2tf(f));
}
#define CP16(smem_u32, gptr) \
    asm volatile("cp.async.cg.shared.global [%0], [%1], 16;" :: "r"(smem_u32), "l"(gptr) : "memory")
#define CP_COMMIT() asm volatile("cp.async.commit_group;" ::: "memory")
#define CP_WAIT(n)  asm volatile("cp.async.wait_group %0;" :: "n"(n) : "memory")

#define MMA_TF32(d, a, b) \
    asm volatile("mma.sync.aligned.m16n8k8.row.col.f32.tf32.tf32.f32 " \
        "{%0,%1,%2,%3}, {%4,%5,%6,%7}, {%8,%9}, {%0,%1,%2,%3};" \
        : "+f"((d)[0]), "+f"((d)[1]), "+f"((d)[2]), "+f"((d)[3]) \
        : "r"((a)[0]), "r"((a)[1]), "r"((a)[2]), "r"((a)[3]), \
          "r"((b)[0]), "r"((b)[1]))

// ============================================================
// tf32 pre-round pass (grid-stride, float4)
// ============================================================
__global__ void round_tf32(const float* __restrict__ in, float* __restrict__ out, int n4) {
    const int stride = gridDim.x * blockDim.x;
    for (int i = blockIdx.x * blockDim.x + threadIdx.x; i < n4; i += stride) {
        float4 v = ((const float4*)in)[i];
        v.x = f2tff(v.x); v.y = f2tff(v.y); v.z = f2tff(v.z); v.w = f2tff(v.w);
        ((float4*)out)[i] = v;
    }
}

// ============================================================
// Tensor-core NT GEMM via mma.sync tf32:
//   C[m,n] = alpha * sum_k A[m,k]*B[n,k]
// 128x128 CTA tile, BK=32, 256 threads (8 warps, 2x4), warp tile 64x32.
// cp.async double-buffered smem, padded stride 36 floats.
// Operands are pre-rounded to tf32 in global (no cvt in mainloop),
// except ARAW=1: A is raw fp32 (attnw) -> cvt at fragment load.
// causal:   skip output blocks fully above the diagonal (scores)
// causal_k: clamp K to (by+1)*128 (AV — attnw zero above diagonal)
// roundc:   round C to tf32 in epilogue (for GEMM-chained intermediates)
// ============================================================
#define SSTR 36                    // padded smem row stride (floats)
#define TILEF (128 * SSTR)         // floats per tile (A or B)
#define STAGEF (2 * TILEF)         // floats per stage (A+B)
#define SMEM_BYTES (2 * STAGEF * 4)

template<int ARAW>
__global__ __launch_bounds__(256, 2) void gemm_mma(
    const float* __restrict__ A, const float* __restrict__ B, float* __restrict__ C,
    int K, int lda, int ldb, int ldc,
    long long sA, long long sB, long long sC,
    float alpha, int causal, int causal_k, int roundc)
{
    const int bx = blockIdx.x, by = blockIdx.y, bz = blockIdx.z;
    if (causal && bx * 128 > by * 128 + 127) return;
    int Keff = K;
    if (causal_k) { int km = (by + 1) * 128; if (km < Keff) Keff = km; }
    const int nch = Keff >> 5;

    extern __shared__ float sm[];

    const int tid = threadIdx.x;
    const int wid = tid >> 5;
    const int lid = tid & 31;
    const int wm  = wid & 1;       // warp row: 0..1 (64 rows each)
    const int wn  = wid >> 1;      // warp col: 0..3 (32 cols each)
    const int g   = lid >> 2;      // 0..7
    const int t   = lid & 3;       // 0..3

    const float* Ab = A + bz * sA + (long long)by * 128 * lda;
    const float* Bb = B + bz * sB + (long long)bx * 128 * ldb;

    // cp.async mapping: each thread copies one row-half (16 floats = 4x float4)
    const int lrow = tid >> 1;            // 0..127
    const int lcb  = (tid & 1) * 16;      // col base: 0 or 16
    const float* ag = Ab + (long long)lrow * lda + lcb;
    const float* bg = Bb + (long long)lrow * ldb + lcb;
    const uint32_t smu = s2u(sm);
    const uint32_t sa_off = (uint32_t)(lrow * SSTR + lcb) * 4;

    auto issue = [&](int c, int s) {
        const uint32_t sab = smu + (uint32_t)(s * STAGEF) * 4 + sa_off;
        const uint32_t sbb = sab + (uint32_t)TILEF * 4;
        const float* ap = ag + c * 32;
        const float* bp = bg + c * 32;
        #pragma unroll
        for (int i = 0; i < 4; i++) {
            CP16(sab + i * 16, ap + i * 4);
            CP16(sbb + i * 16, bp + i * 4);
        }
    };

    float acc[4][4][4];
    #pragma unroll
    for (int mf = 0; mf < 4; mf++)
        #pragma unroll
        for (int nf = 0; nf < 4; nf++)
            #pragma unroll
            for (int i = 0; i < 4; i++) acc[mf][nf][i] = 0.0f;

    issue(0, 0); CP_COMMIT();
    if (nch > 1) { issue(1, 1); CP_COMMIT(); }

    for (int c = 0; c < nch; c++) {
        const int s = c & 1;
        if (c + 1 < nch) { CP_WAIT(1); } else { CP_WAIT(0); }
        __syncthreads();

        const float* As = sm + s * STAGEF + (wm * 64 + g) * SSTR;
        const float* Bs = sm + s * STAGEF + TILEF + (wn * 32 + g) * SSTR;

        #pragma unroll
        for (int kk = 0; kk < 4; kk++) {
            const int kb = kk * 8 + t;
            uint32_t af[4][4], bf[4][2];
            #pragma unroll
            for (int mf = 0; mf < 4; mf++) {
                const float* p = As + mf * 16 * SSTR + kb;
                if (ARAW) {
                    af[mf][0] = f2tf(p[0]);
                    af[mf][1] = f2tf(p[8 * SSTR]);
                    af[mf][2] = f2tf(p[4]);
                    af[mf][3] = f2tf(p[8 * SSTR + 4]);
                } else {
                    af[mf][0] = __float_as_uint(p[0]);
                    af[mf][1] = __float_as_uint(p[8 * SSTR]);
                    af[mf][2] = __float_as_uint(p[4]);
                    af[mf][3] = __float_as_uint(p[8 * SSTR + 4]);
                }
            }
            #pragma unroll
            for (int nf = 0; nf < 4; nf++) {
                const float* p = Bs + nf * 8 * SSTR + kb;
                bf[nf][0] = __float_as_uint(p[0]);
                bf[nf][1] = __float_as_uint(p[4]);
            }
            #pragma unroll
            for (int mf = 0; mf < 4; mf++)
                #pragma unroll
                for (int nf = 0; nf < 4; nf++)
                    MMA_TF32(acc[mf][nf], af[mf], bf[nf]);
        }
        __syncthreads();
        if (c + 2 < nch) { issue(c + 2, s); CP_COMMIT(); }
    }

    // epilogue: direct global store (float2 per fragment half-row)
    float* Cb = C + bz * sC;
    #pragma unroll
    for (int mf = 0; mf < 4; mf++) {
        const int r0 = by * 128 + wm * 64 + mf * 16 + g;
        #pragma unroll
        for (int nf = 0; nf < 4; nf++) {
            const int c0 = bx * 128 + wn * 32 + nf * 8 + 2 * t;
            float* cp = Cb + (long long)r0 * ldc + c0;
            float2 v0, v1;
            v0.x = alpha * acc[mf][nf][0];
            v0.y = alpha * acc[mf][nf][1];
            v1.x = alpha * acc[mf][nf][2];
            v1.y = alpha * acc[mf][nf][3];
            if (roundc) {
                v0.x = f2tff(v0.x); v0.y = f2tff(v0.y);
                v1.x = f2tff(v1.x); v1.y = f2tff(v1.y);
            }
            *(float2*)cp = v0;
            *(float2*)(cp + 8 * ldc) = v1;
        }
    }
}

// ============================================================
// RoPE + rearrange: qkv(s,5120) -> q(h,s,d), k(h,s,d) repl, vT(h,d,s) repl
// All outputs tf32-rounded (they are GEMM operands only).
// ============================================================
__global__ void rope_kernel(const float* __restrict__ qkv,
                            const float* __restrict__ cosb,
                            const float* __restrict__ sinb)
{
    const int s = blockIdx.x;
    const float* row = qkv + (long long)s * QKV_N;
    const float* cs = cosb + (long long)s * ROTD;
    const float* sn = sinb + (long long)s * ROTD;

    for (int idx = threadIdx.x; idx < QKV_N; idx += blockDim.x) {
        const int d = idx & (HD - 1);
        float x = row[idx];
        float outv = x;
        if (idx < NH * HD + NKV * HD) {
            if (d < ROTD / 2)       outv = x * cs[d] - row[idx + ROTD / 2] * sn[d];
            else if (d < ROTD)      outv = x * cs[d] + row[idx - ROTD / 2] * sn[d];
        }
        outv = f2tff(outv);
        if (idx < NH * HD) {
            const int h = idx >> 7;
            g_q[((long long)h * SEQ + s) * HD + d] = outv;
        } else if (idx < NH * HD + NKV * HD) {
            const int kh = (idx - NH * HD) >> 7;
            #pragma unroll
            for (int r = 0; r < NREP; r++)
                g_k[((long long)(kh * NREP + r) * SEQ + s) * HD + d] = outv;
        } else {
            const int vh = (idx - NH * HD - NKV * HD) >> 7;
            #pragma unroll
            for (int r = 0; r < NREP; r++)
                g_vt[((long long)(vh * NREP + r) * HD + d) * SEQ + s] = outv;
        }
    }
}

// ============================================================
// Row softmax with causal zeroing. One block (256 thr) per (q,h) row.
// ============================================================
__global__ __launch_bounds__(256) void softmax_kernel(float* __restrict__ attnw)
{
    const int q = blockIdx.x;
    const int h = blockIdx.y;
    float* row = attnw + ((long long)h * SEQ + q) * SEQ;
    const int n = q + 1;
    const int tid = threadIdx.x;

    __shared__ float red[256];

    float vals[8];
    float m = -1e30f;
    #pragma unroll
    for (int i = 0; i < 8; i++) {
        const int idx = tid + i * 256;
        vals[i] = (idx < n) ? row[idx] : -1e30f;
        m = fmaxf(m, vals[i]);
    }
    red[tid] = m;
    __syncthreads();
    for (int s2 = 128; s2 > 0; s2 >>= 1) {
        if (tid < s2) red[tid] = fmaxf(red[tid], red[tid + s2]);
        __syncthreads();
    }
    m = red[0];
    __syncthreads();

    float sum = 0.0f;
    #pragma unroll
    for (int i = 0; i < 8; i++) {
        const int idx = tid + i * 256;
        vals[i] = (idx < n) ? expf(vals[i] - m) : 0.0f;
        sum += vals[i];
    }
    red[tid] = sum;
    __syncthreads();
    for (int s2 = 128; s2 > 0; s2 >>= 1) {
        if (tid < s2) red[tid] += red[tid + s2];
        __syncthreads();
    }
    const float inv = 1.0f / red[0];

    #pragma unroll
    for (int i = 0; i < 8; i++) {
        const int idx = tid + i * 256;
        row[idx] = vals[i] * inv;
    }
}

// ============================================================
extern "C" void kernel_launch(void* const* d_in, const int* in_sizes, int n_in,
                              void* d_out, int out_size)
{
    const float* hidden = (const float*)d_in[0];
    const float* cosb   = (const float*)d_in[1];
    const float* sinb   = (const float*)d_in[2];
    // d_in[3] = attention_mask (causal; applied analytically)
    const float* w_qkv  = (const float*)d_in[4];
    const float* w_o    = (const float*)d_in[5];

    float* out   = (float*)d_out;                 // (2048,3072)
    float* attnw = out + (long long)SEQ * HID;    // (24,2048,2048)

    float *qkvb, *qb, *kb, *vtb, *aob, *hidb, *wqkvb, *wob;
    cudaGetSymbolAddress((void**)&qkvb,  g_qkv);
    cudaGetSymbolAddress((void**)&qb,    g_q);
    cudaGetSymbolAddress((void**)&kb,    g_k);
    cudaGetSymbolAddress((void**)&vtb,   g_vt);
    cudaGetSymbolAddress((void**)&aob,   g_ao);
    cudaGetSymbolAddress((void**)&hidb,  g_hid);
    cudaGetSymbolAddress((void**)&wqkvb, g_wqkv);
    cudaGetSymbolAddress((void**)&wob,   g_wo);

    static int configured = 0;
    if (!configured) {
        cudaFuncSetAttribute(gemm_mma<0>, cudaFuncAttributeMaxDynamicSharedMemorySize, SMEM_BYTES);
        cudaFuncSetAttribute(gemm_mma<1>, cudaFuncAttributeMaxDynamicSharedMemorySize, SMEM_BYTES);
        configured = 1;
    }

    const float scale = 0.08838834764831843f;  // 128^-0.5
    dim3 blk(256);
    const int RG = 1184;  // 8 * 148 blocks for round passes

    // 0) tf32 pre-round of GEMM operands
    round_tf32<<<RG, 256>>>(hidden, hidb,  SEQ * HID / 4);
    round_tf32<<<RG, 256>>>(w_qkv,  wqkvb, QKV_N * HID / 4);
    round_tf32<<<RG, 256>>>(w_o,    wob,   HID * HID / 4);

    // 1) QKV projection: (2048x3072) x (5120x3072)^T -> (2048x5120)
    gemm_mma<0><<<dim3(QKV_N / 128, SEQ / 128, 1), blk, SMEM_BYTES>>>(
        hidb, wqkvb, qkvb, HID, HID, HID, QKV_N,
        0, 0, 0, 1.0f, 0, 0, 0);

    // 2) RoPE + rearrange + GQA replicate + V transpose (outputs tf32-rounded)
    rope_kernel<<<SEQ, 512>>>(qkvb, cosb, sinb);

    // 3) Scores: per head, (2048x128) x (2048x128)^T * scale, causal block-skip
    gemm_mma<0><<<dim3(SEQ / 128, SEQ / 128, NH), blk, SMEM_BYTES>>>(
        qb, kb, attnw, HD, HD, HD, SEQ,
        (long long)SEQ * HD, (long long)SEQ * HD, (long long)SEQ * SEQ,
        scale, 1, 0, 0);

    // 4) Causal softmax (writes the attn_weights output in place, full fp32)
    softmax_kernel<<<dim3(SEQ, NH), blk>>>(attnw);

    // 5) AV: per head, (2048x2048) x (128x2048)^T, K clamped causally.
    //    A = attnw raw fp32 (cvt in-kernel); C rounded for out-proj.
    gemm_mma<1><<<dim3(HD / 128, SEQ / 128, NH), blk, SMEM_BYTES>>>(
        attnw, vtb, aob, SEQ, SEQ, SEQ, HID,
        (long long)SEQ * SEQ, (long long)HD * SEQ, (long long)HD,
        1.0f, 0, 1, 1);

    // 6) Output projection: (2048x3072) x (3072x3072)^T -> out
    gemm_mma<0><<<dim3(HID / 128, SEQ / 128, 1), blk, SMEM_BYTES>>>(
        aob, wob, out, HID, HID, HID, HID,
        0, 0, 0, 1.0f, 0, 0, 0);
}